// round 1
// baseline (speedup 1.0000x reference)
#include <cuda_runtime.h>
#include <cuda_bf16.h>

// NADE collapse:
//   out[i,0] = sigmoid(S0[0])
//   out[i,d] = x[i,d-1] ? sigmoid(S1[d]) : sigmoid(S0[d])   (d >= 1)
// with
//   S0[d] = sum_h sigmoid(c[h])            * (V[d,h] + b[d])
//   S1[d] = sum_h sigmoid(W[h,d-1] + c[h]) * (V[d,h] + b[d])
// Valid because x is exactly binary (round(uniform)) and the reference scan
// resets the carry to c each step (a_next = x_d*w_d + c, no accumulation).

#define D_DIM 784
#define H_DIM 1024

__device__ float g_P0[D_DIM];
__device__ float g_P1[D_DIM];

__device__ __forceinline__ float sigmoidf_fast(float v) {
    return 1.0f / (1.0f + __expf(-v));
}

// ---------------------------------------------------------------------------
// Kernel 1: one block per output column d. Reduce over H.
// ---------------------------------------------------------------------------
__global__ void nade_precompute(const float* __restrict__ V,
                                const float* __restrict__ b,
                                const float* __restrict__ W,
                                const float* __restrict__ c) {
    const int d   = blockIdx.x;
    const int tid = threadIdx.x;

    const float bd = __ldg(&b[d]);
    float s0 = 0.0f;
    float s1 = 0.0f;

    #pragma unroll 4
    for (int h = tid; h < H_DIM; h += 256) {
        const float vb = __ldg(&V[d * H_DIM + h]) + bd;
        const float ch = __ldg(&c[h]);
        s0 += sigmoidf_fast(ch) * vb;
        if (d > 0) {
            const float w = __ldg(&W[h * D_DIM + (d - 1)]);
            s1 += sigmoidf_fast(w + ch) * vb;
        }
    }

    // warp reduce
    #pragma unroll
    for (int off = 16; off > 0; off >>= 1) {
        s0 += __shfl_down_sync(0xFFFFFFFFu, s0, off);
        s1 += __shfl_down_sync(0xFFFFFFFFu, s1, off);
    }

    __shared__ float sm0[8];
    __shared__ float sm1[8];
    const int warp = tid >> 5;
    const int lane = tid & 31;
    if (lane == 0) { sm0[warp] = s0; sm1[warp] = s1; }
    __syncthreads();

    if (warp == 0) {
        s0 = (lane < 8) ? sm0[lane] : 0.0f;
        s1 = (lane < 8) ? sm1[lane] : 0.0f;
        #pragma unroll
        for (int off = 4; off > 0; off >>= 1) {
            s0 += __shfl_down_sync(0xFFFFFFFFu, s0, off);
            s1 += __shfl_down_sync(0xFFFFFFFFu, s1, off);
        }
        if (lane == 0) {
            g_P0[d] = sigmoidf_fast(s0);
            g_P1[d] = (d > 0) ? sigmoidf_fast(s1) : 0.0f;
        }
    }
}

// ---------------------------------------------------------------------------
// Kernel 2: streaming select. One thread -> one float4 of the output row.
// D = 784 is divisible by 4, so each float4 stays inside one row.
// out[i,d] needs x[i,d-1]: one vector load (d0..d0+3) covers lanes 1..3,
// one scalar load covers lane 0 (same cache lines as the neighbor's vector).
// ---------------------------------------------------------------------------
__global__ void __launch_bounds__(256) nade_main(const float* __restrict__ x,
                                                 float* __restrict__ out,
                                                 int n4) {
    const int t = blockIdx.x * blockDim.x + threadIdx.x;
    if (t >= n4) return;

    const int e  = t << 2;           // flat element index, multiple of 4
    const int i  = e / D_DIM;        // mult-shift by compiler
    const int d0 = e - i * D_DIM;    // 0..780, multiple of 4

    const float4 xv = *reinterpret_cast<const float4*>(x + e);

    float4 o;
    if (d0 == 0) {
        o.x = g_P0[0];
    } else {
        const float xm1 = __ldg(&x[e - 1]);
        o.x = (xm1 != 0.0f) ? g_P1[d0] : g_P0[d0];
    }
    o.y = (xv.x != 0.0f) ? g_P1[d0 + 1] : g_P0[d0 + 1];
    o.z = (xv.y != 0.0f) ? g_P1[d0 + 2] : g_P0[d0 + 2];
    o.w = (xv.z != 0.0f) ? g_P1[d0 + 3] : g_P0[d0 + 3];

    *reinterpret_cast<float4*>(out + e) = o;
}

// ---------------------------------------------------------------------------
extern "C" void kernel_launch(void* const* d_in, const int* in_sizes, int n_in,
                              void* d_out, int out_size) {
    const float* x = (const float*)d_in[0];
    const float* V = (const float*)d_in[1];
    const float* b = (const float*)d_in[2];
    const float* W = (const float*)d_in[3];
    const float* c = (const float*)d_in[4];
    float* out = (float*)d_out;

    nade_precompute<<<D_DIM, 256>>>(V, b, W, c);

    const int n4 = out_size / 4;                 // 16384*784/4 = 3,211,264
    const int blocks = (n4 + 255) / 256;         // 12,544
    nade_main<<<blocks, 256>>>(x, out, n4);
}

// round 2
// speedup vs baseline: 1.2443x; 1.2443x over previous
#include <cuda_runtime.h>
#include <cuda_bf16.h>

// NADE collapse (x is exactly binary; reference scan resets carry to c):
//   out[i,0] = sigmoid(S0[0])
//   out[i,d] = x[i,d-1] ? sigmoid(S1[d]) : sigmoid(S0[d])   (d >= 1)
//   S0[d] = sum_h sigmoid(c[h])            * (V[d,h] + b[d])
//   S1[d] = sum_h sigmoid(W[h,d-1] + c[h]) * (V[d,h] + b[d])
// Table packed as T[d] = {P0[d], P1[d]-P0[d]}; main kernel: out = fma(xprev, diff, P0).
// For d==0, diff=0 -> out = P0[0] regardless of xprev.

#define D_DIM 784
#define H_DIM 1024

__device__ __align__(16) float2 g_T[D_DIM];   // {P0, P1-P0}
__device__ float g_sigc[H_DIM];               // sigmoid(c[h])

__device__ __forceinline__ float tanh_fast(float v) {
    float y;
    asm("tanh.approx.f32 %0, %1;" : "=f"(y) : "f"(v));
    return y;
}
__device__ __forceinline__ float sigmoid_tanh(float v) {
    return fmaf(tanh_fast(0.5f * v), 0.5f, 0.5f);
}

// ---------------------------------------------------------------------------
// Kernel 0: sigc[h] = sigmoid(c[h]).  One block, 1024 threads.
// ---------------------------------------------------------------------------
__global__ void nade_sigc(const float* __restrict__ c) {
    const int h = threadIdx.x;
    g_sigc[h] = sigmoid_tanh(c[h]);
}

// ---------------------------------------------------------------------------
// Kernel 1: per-d table build. 784 blocks x 256 threads; each thread owns
// 4 consecutive h (one float4 of V / sigc / c, 4 strided W scalars).
// ---------------------------------------------------------------------------
__global__ void __launch_bounds__(256) nade_tables(const float* __restrict__ V,
                                                   const float* __restrict__ b,
                                                   const float* __restrict__ W,
                                                   const float* __restrict__ c) {
    const int d   = blockIdx.x;
    const int tid = threadIdx.x;
    const int h0  = tid * 4;

    const float  bd = __ldg(&b[d]);
    const float4 v4 = *reinterpret_cast<const float4*>(V + d * H_DIM + h0);
    const float4 s4 = *reinterpret_cast<const float4*>(g_sigc + h0);

    const float vb0 = v4.x + bd, vb1 = v4.y + bd, vb2 = v4.z + bd, vb3 = v4.w + bd;

    float s0 = s4.x * vb0 + s4.y * vb1 + s4.z * vb2 + s4.w * vb3;

    float s1 = 0.0f;
    if (d > 0) {
        const float4 c4 = *reinterpret_cast<const float4*>(c + h0);
        const int wcol = d - 1;
        const float w0 = __ldg(&W[(h0 + 0) * D_DIM + wcol]);
        const float w1 = __ldg(&W[(h0 + 1) * D_DIM + wcol]);
        const float w2 = __ldg(&W[(h0 + 2) * D_DIM + wcol]);
        const float w3 = __ldg(&W[(h0 + 3) * D_DIM + wcol]);
        s1  = sigmoid_tanh(w0 + c4.x) * vb0;
        s1 += sigmoid_tanh(w1 + c4.y) * vb1;
        s1 += sigmoid_tanh(w2 + c4.z) * vb2;
        s1 += sigmoid_tanh(w3 + c4.w) * vb3;
    }

    // block reduce (256 -> 1)
    #pragma unroll
    for (int off = 16; off > 0; off >>= 1) {
        s0 += __shfl_down_sync(0xFFFFFFFFu, s0, off);
        s1 += __shfl_down_sync(0xFFFFFFFFu, s1, off);
    }
    __shared__ float sm0[8], sm1[8];
    const int warp = tid >> 5, lane = tid & 31;
    if (lane == 0) { sm0[warp] = s0; sm1[warp] = s1; }
    __syncthreads();
    if (warp == 0) {
        s0 = (lane < 8) ? sm0[lane] : 0.0f;
        s1 = (lane < 8) ? sm1[lane] : 0.0f;
        #pragma unroll
        for (int off = 4; off > 0; off >>= 1) {
            s0 += __shfl_down_sync(0xFFFFFFFFu, s0, off);
            s1 += __shfl_down_sync(0xFFFFFFFFu, s1, off);
        }
        if (lane == 0) {
            const float p0 = sigmoid_tanh(s0);
            float diff = 0.0f;
            if (d > 0) diff = sigmoid_tanh(s1) - p0;
            g_T[d] = make_float2(p0, diff);
        }
    }
}

// ---------------------------------------------------------------------------
// Kernel 2: streaming select. Thread -> one float4 of output. Grid is exact
// (16384*784/4 = 3,211,264 = 12544*256), so no bounds checks; warps full.
// Previous-element value comes from __shfl_up of the neighbor lane's xv.w;
// only lane 0 (with d0 != 0) does a scalar load.
// ---------------------------------------------------------------------------
__global__ void __launch_bounds__(256) nade_main(const float* __restrict__ x,
                                                 float* __restrict__ out) {
    const int t  = blockIdx.x * 256 + threadIdx.x;
    const int e  = t << 2;            // flat index, multiple of 4
    const int i  = e / D_DIM;
    const int d0 = e - i * D_DIM;     // 0..780, multiple of 4

    const float4 xv = __ldcs(reinterpret_cast<const float4*>(x + e));

    float prev = __shfl_up_sync(0xFFFFFFFFu, xv.w, 1);
    if ((threadIdx.x & 31) == 0 && d0 != 0) prev = __ldg(&x[e - 1]);
    // if d0 == 0, T[0].diff == 0 so prev is irrelevant (finite garbage ok)

    const float4 ta = *reinterpret_cast<const float4*>(&g_T[d0]);      // {P0[d0],df[d0],P0[d0+1],df[d0+1]}
    const float4 tb = *reinterpret_cast<const float4*>(&g_T[d0 + 2]);  // {P0[d0+2],df[d0+2],P0[d0+3],df[d0+3]}

    float4 o;
    o.x = fmaf(prev, ta.y, ta.x);
    o.y = fmaf(xv.x, ta.w, ta.z);
    o.z = fmaf(xv.y, tb.y, tb.x);
    o.w = fmaf(xv.z, tb.w, tb.z);

    __stcs(reinterpret_cast<float4*>(out + e), o);
}

// ---------------------------------------------------------------------------
extern "C" void kernel_launch(void* const* d_in, const int* in_sizes, int n_in,
                              void* d_out, int out_size) {
    const float* x = (const float*)d_in[0];
    const float* V = (const float*)d_in[1];
    const float* b = (const float*)d_in[2];
    const float* W = (const float*)d_in[3];
    const float* c = (const float*)d_in[4];
    float* out = (float*)d_out;

    nade_sigc<<<1, H_DIM>>>(c);
    nade_tables<<<D_DIM, 256>>>(V, b, W, c);

    const int n4 = out_size / 4;           // 3,211,264
    nade_main<<<n4 / 256, 256>>>(x, out);
}

// round 3
// speedup vs baseline: 1.3464x; 1.0820x over previous
#include <cuda_runtime.h>
#include <cuda_bf16.h>

// NADE collapse (x is exactly binary; reference scan resets carry to c):
//   out[i,0] = sigmoid(S0[0])
//   out[i,d] = x[i,d-1] ? sigmoid(S1[d]) : sigmoid(S0[d])   (d >= 1)
//   S0[d] = sum_h sigmoid(c[h])            * (V[d,h] + b[d])
//   S1[d] = sum_h sigmoid(W[h,d-1] + c[h]) * (V[d,h] + b[d])
// Table packed as T[d] = {P0[d], P1[d]-P0[d]}; main: out = fma(xprev, diff, P0).
// d==0 has diff=0 so any finite xprev yields P0[0].
//
// Two kernels linked by PDL: nade_main launches early (programmatic stream
// serialization), does index math + x load, then grid-sync before reading g_T.

#define D_DIM 784
#define H_DIM 1024

__device__ __align__(16) float2 g_T[D_DIM];   // {P0, P1-P0}

__device__ __forceinline__ float tanh_fast(float v) {
    float y;
    asm("tanh.approx.f32 %0, %1;" : "=f"(y) : "f"(v));
    return y;
}
__device__ __forceinline__ float sigmoid_tanh(float v) {
    return fmaf(tanh_fast(0.5f * v), 0.5f, 0.5f);
}

// ---------------------------------------------------------------------------
// Kernel 1: per-d table build (sigmoid(c) fused inline). 784 blocks x 256 thr;
// each thread owns 4 consecutive h (one float4 of V and c, 4 strided W scalars).
// ---------------------------------------------------------------------------
__global__ void __launch_bounds__(256) nade_tables(const float* __restrict__ V,
                                                   const float* __restrict__ b,
                                                   const float* __restrict__ W,
                                                   const float* __restrict__ c) {
    const int d   = blockIdx.x;
    const int tid = threadIdx.x;
    const int h0  = tid * 4;

    const float  bd = __ldg(&b[d]);
    const float4 v4 = *reinterpret_cast<const float4*>(V + d * H_DIM + h0);
    const float4 c4 = *reinterpret_cast<const float4*>(c + h0);

    const float vb0 = v4.x + bd, vb1 = v4.y + bd, vb2 = v4.z + bd, vb3 = v4.w + bd;

    float s0;
    s0  = sigmoid_tanh(c4.x) * vb0;
    s0 += sigmoid_tanh(c4.y) * vb1;
    s0 += sigmoid_tanh(c4.z) * vb2;
    s0 += sigmoid_tanh(c4.w) * vb3;

    float s1 = 0.0f;
    if (d > 0) {
        const int wcol = d - 1;
        const float w0 = __ldg(&W[(h0 + 0) * D_DIM + wcol]);
        const float w1 = __ldg(&W[(h0 + 1) * D_DIM + wcol]);
        const float w2 = __ldg(&W[(h0 + 2) * D_DIM + wcol]);
        const float w3 = __ldg(&W[(h0 + 3) * D_DIM + wcol]);
        s1  = sigmoid_tanh(w0 + c4.x) * vb0;
        s1 += sigmoid_tanh(w1 + c4.y) * vb1;
        s1 += sigmoid_tanh(w2 + c4.z) * vb2;
        s1 += sigmoid_tanh(w3 + c4.w) * vb3;
    }

    // block reduce (256 -> 1)
    #pragma unroll
    for (int off = 16; off > 0; off >>= 1) {
        s0 += __shfl_down_sync(0xFFFFFFFFu, s0, off);
        s1 += __shfl_down_sync(0xFFFFFFFFu, s1, off);
    }
    __shared__ float sm0[8], sm1[8];
    const int warp = tid >> 5, lane = tid & 31;
    if (lane == 0) { sm0[warp] = s0; sm1[warp] = s1; }
    __syncthreads();
    if (warp == 0) {
        s0 = (lane < 8) ? sm0[lane] : 0.0f;
        s1 = (lane < 8) ? sm1[lane] : 0.0f;
        #pragma unroll
        for (int off = 4; off > 0; off >>= 1) {
            s0 += __shfl_down_sync(0xFFFFFFFFu, s0, off);
            s1 += __shfl_down_sync(0xFFFFFFFFu, s1, off);
        }
        if (lane == 0) {
            const float p0 = sigmoid_tanh(s0);
            float diff = 0.0f;
            if (d > 0) diff = sigmoid_tanh(s1) - p0;
            g_T[d] = make_float2(p0, diff);
        }
    }

    // Allow the dependent nade_main grid to begin its pre-sync portion.
    cudaTriggerProgrammaticLaunchCompletion();
}

// ---------------------------------------------------------------------------
// Kernel 2: streaming select. Thread -> one float4 of output. Grid exact
// (16384*784/4 = 3,211,264 = 12544*256): no bounds checks, full warps.
// Previous-element value via __shfl_up of neighbor's xv.w; only lane 0
// (with d0 != 0) does a scalar load. Pre-sync portion: index math + x load.
// ---------------------------------------------------------------------------
__global__ void __launch_bounds__(256) nade_main(const float* __restrict__ x,
                                                 float* __restrict__ out) {
    const int t  = blockIdx.x * 256 + threadIdx.x;
    const int e  = t << 2;            // flat index, multiple of 4
    const int i  = e / D_DIM;
    const int d0 = e - i * D_DIM;     // 0..780, multiple of 4

    // x is an input tensor, independent of g_T: load before the grid sync.
    const float4 xv = *reinterpret_cast<const float4*>(x + e);

    float prev = __shfl_up_sync(0xFFFFFFFFu, xv.w, 1);
    if ((threadIdx.x & 31) == 0 && d0 != 0) prev = __ldg(&x[e - 1]);
    // d0 == 0: T[0].diff == 0, prev value irrelevant (finite).

    // Wait for nade_tables' writes to g_T to be visible.
    cudaGridDependencySynchronize();

    const float4 ta = *reinterpret_cast<const float4*>(&g_T[d0]);
    const float4 tb = *reinterpret_cast<const float4*>(&g_T[d0 + 2]);

    float4 o;
    o.x = fmaf(prev, ta.y, ta.x);
    o.y = fmaf(xv.x, ta.w, ta.z);
    o.z = fmaf(xv.y, tb.y, tb.x);
    o.w = fmaf(xv.z, tb.w, tb.z);

    __stcs(reinterpret_cast<float4*>(out + e), o);   // out never re-read
}

// ---------------------------------------------------------------------------
extern "C" void kernel_launch(void* const* d_in, const int* in_sizes, int n_in,
                              void* d_out, int out_size) {
    const float* x = (const float*)d_in[0];
    const float* V = (const float*)d_in[1];
    const float* b = (const float*)d_in[2];
    const float* W = (const float*)d_in[3];
    const float* c = (const float*)d_in[4];
    float* out = (float*)d_out;

    nade_tables<<<D_DIM, 256>>>(V, b, W, c);

    const int n4 = out_size / 4;           // 3,211,264
    cudaLaunchConfig_t cfg = {};
    cfg.gridDim  = dim3(n4 / 256);         // 12,544
    cfg.blockDim = dim3(256);
    cfg.dynamicSmemBytes = 0;
    cfg.stream = 0;
    cudaLaunchAttribute attr[1];
    attr[0].id = cudaLaunchAttributeProgrammaticStreamSerialization;
    attr[0].val.programmaticStreamSerializationAllowed = 1;
    cfg.attrs = attr;
    cfg.numAttrs = 1;
    cudaLaunchKernelEx(&cfg, nade_main, x, out);
}

// round 4
// speedup vs baseline: 1.7091x; 1.2694x over previous
#include <cuda_runtime.h>
#include <cuda_bf16.h>

// NADE collapse (x is exactly binary; reference scan resets carry to c):
//   out[i,0] = sigmoid(S0[0])
//   out[i,d] = x[i,d-1] ? sigmoid(S1[d]) : sigmoid(S0[d])   (d >= 1)
//   S0[d] = sum_h sigmoid(c[h])            * (V[d,h] + b[d])
//   S1[d] = sum_h sigmoid(W[h,d-1] + c[h]) * (V[d,h] + b[d])
// Table packed as T[d] = {P0[d], P1[d]-P0[d]}; main: out = fma(xprev, diff, P0).
// d==0 has diff=0 so any finite xprev yields P0[0].

#define D_DIM 784
#define H_DIM 1024
#define CHUNK 3211264            // 4096 rows * 784: flat-element stride between chunks
#define NQ    802816             // float4s per chunk (= thread count of nade_main)

__device__ __align__(16) float2 g_T[D_DIM];   // {P0, P1-P0}

__device__ __forceinline__ float tanh_fast(float v) {
    float y;
    asm("tanh.approx.f32 %0, %1;" : "=f"(y) : "f"(v));
    return y;
}
__device__ __forceinline__ float sigmoid_tanh(float v) {
    return fmaf(tanh_fast(0.5f * v), 0.5f, 0.5f);
}

// ---------------------------------------------------------------------------
// Kernel 1: table build. 196 blocks; block j owns d in [4j, 4j+4).
// Thread owns 4 consecutive h. W columns [4j-4, 4j+4) read as two aligned
// float4s per h-row (4x fewer L1 wavefronts than per-column scalar loads).
// ---------------------------------------------------------------------------
__global__ void __launch_bounds__(256) nade_tables(const float* __restrict__ V,
                                                   const float* __restrict__ b,
                                                   const float* __restrict__ W,
                                                   const float* __restrict__ c) {
    const int j   = blockIdx.x;
    const int tid = threadIdx.x;
    const int h0  = tid * 4;

    const float4 c4 = *reinterpret_cast<const float4*>(c + h0);
    const float sc0 = sigmoid_tanh(c4.x);
    const float sc1 = sigmoid_tanh(c4.y);
    const float sc2 = sigmoid_tanh(c4.z);
    const float sc3 = sigmoid_tanh(c4.w);

    const float4 b4 = __ldg(reinterpret_cast<const float4*>(b + 4 * j));
    float bd[4] = {b4.x, b4.y, b4.z, b4.w};

    // W cols [4j-4, 4j+4): w[hh][idx] = W[h0+hh][4j-4+idx], idx 0..7.
    // Needed: wcol(k) = 4j+k-1 -> idx k+3 (k=0..3). j==0,k==0 unused (diff=0).
    float w[4][8];
    const int base = 4 * j - 4;
    #pragma unroll
    for (int hh = 0; hh < 4; hh++) {
        const float* wr = W + (h0 + hh) * D_DIM;
        if (j > 0) {
            const float4 a = __ldg(reinterpret_cast<const float4*>(wr + base));
            w[hh][0] = a.x; w[hh][1] = a.y; w[hh][2] = a.z; w[hh][3] = a.w;
        } else {
            w[hh][0] = 0.f; w[hh][1] = 0.f; w[hh][2] = 0.f; w[hh][3] = 0.f;
        }
        const float4 q = __ldg(reinterpret_cast<const float4*>(wr + base + 4));
        w[hh][4] = q.x; w[hh][5] = q.y; w[hh][6] = q.z; w[hh][7] = q.w;
    }

    float s0[4], s1[4];
    #pragma unroll
    for (int k = 0; k < 4; k++) {
        const float4 v4 = __ldg(reinterpret_cast<const float4*>(V + (4 * j + k) * H_DIM + h0));
        const float vb0 = v4.x + bd[k];
        const float vb1 = v4.y + bd[k];
        const float vb2 = v4.z + bd[k];
        const float vb3 = v4.w + bd[k];
        s0[k] = sc0 * vb0 + sc1 * vb1 + sc2 * vb2 + sc3 * vb3;
        float t;
        t  = sigmoid_tanh(w[0][k + 3] + c4.x) * vb0;
        t += sigmoid_tanh(w[1][k + 3] + c4.y) * vb1;
        t += sigmoid_tanh(w[2][k + 3] + c4.z) * vb2;
        t += sigmoid_tanh(w[3][k + 3] + c4.w) * vb3;
        s1[k] = t;
    }

    // block reduce 8 values (256 -> 1 each)
    #pragma unroll
    for (int off = 16; off > 0; off >>= 1) {
        #pragma unroll
        for (int k = 0; k < 4; k++) {
            s0[k] += __shfl_down_sync(0xFFFFFFFFu, s0[k], off);
            s1[k] += __shfl_down_sync(0xFFFFFFFFu, s1[k], off);
        }
    }
    __shared__ float sm[8][8];
    const int warp = tid >> 5, lane = tid & 31;
    if (lane == 0) {
        #pragma unroll
        for (int k = 0; k < 4; k++) {
            sm[warp][k]     = s0[k];
            sm[warp][4 + k] = s1[k];
        }
    }
    __syncthreads();
    if (tid < 4) {
        float a0 = 0.f, a1 = 0.f;
        #pragma unroll
        for (int wq = 0; wq < 8; wq++) {
            a0 += sm[wq][tid];
            a1 += sm[wq][4 + tid];
        }
        const int d = 4 * j + tid;
        const float p0 = sigmoid_tanh(a0);
        const float diff = (d > 0) ? (sigmoid_tanh(a1) - p0) : 0.f;
        g_T[d] = make_float2(p0, diff);
    }

    cudaTriggerProgrammaticLaunchCompletion();
}

// ---------------------------------------------------------------------------
// Kernel 2: streaming select, 4 chunks per thread at flat stride CHUNK
// (a multiple of D_DIM, so all chunks share d0 and the same lane/row-boundary
// structure). Table loads amortize 4x. Grid exact: 802,816 threads.
// ---------------------------------------------------------------------------
__global__ void __launch_bounds__(256) nade_main(const float* __restrict__ x,
                                                 float* __restrict__ out) {
    const int q  = blockIdx.x * 256 + threadIdx.x;   // [0, NQ)
    const int e0 = q << 2;                           // flat index, multiple of 4
    const int i  = e0 / D_DIM;
    const int d0 = e0 - i * D_DIM;                   // 0..780, multiple of 4

    // x loads are independent of g_T: issue before the PDL grid sync.
    const float4 xv0 = *reinterpret_cast<const float4*>(x + e0);
    const float4 xv1 = *reinterpret_cast<const float4*>(x + e0 + CHUNK);
    const float4 xv2 = *reinterpret_cast<const float4*>(x + e0 + 2 * CHUNK);
    const float4 xv3 = *reinterpret_cast<const float4*>(x + e0 + 3 * CHUNK);

    float p0 = __shfl_up_sync(0xFFFFFFFFu, xv0.w, 1);
    float p1 = __shfl_up_sync(0xFFFFFFFFu, xv1.w, 1);
    float p2 = __shfl_up_sync(0xFFFFFFFFu, xv2.w, 1);
    float p3 = __shfl_up_sync(0xFFFFFFFFu, xv3.w, 1);
    if (((threadIdx.x & 31) == 0) && (d0 != 0)) {
        p0 = __ldg(&x[e0 - 1]);
        p1 = __ldg(&x[e0 + CHUNK - 1]);
        p2 = __ldg(&x[e0 + 2 * CHUNK - 1]);
        p3 = __ldg(&x[e0 + 3 * CHUNK - 1]);
    }
    // d0 == 0: T[0].diff == 0, prev value irrelevant (finite).

    cudaGridDependencySynchronize();

    const float4 ta = *reinterpret_cast<const float4*>(&g_T[d0]);      // {P0,df}[d0], {P0,df}[d0+1]
    const float4 tb = *reinterpret_cast<const float4*>(&g_T[d0 + 2]);

    float4 o;
    o.x = fmaf(p0,    ta.y, ta.x);
    o.y = fmaf(xv0.x, ta.w, ta.z);
    o.z = fmaf(xv0.y, tb.y, tb.x);
    o.w = fmaf(xv0.z, tb.w, tb.z);
    __stcs(reinterpret_cast<float4*>(out + e0), o);

    o.x = fmaf(p1,    ta.y, ta.x);
    o.y = fmaf(xv1.x, ta.w, ta.z);
    o.z = fmaf(xv1.y, tb.y, tb.x);
    o.w = fmaf(xv1.z, tb.w, tb.z);
    __stcs(reinterpret_cast<float4*>(out + e0 + CHUNK), o);

    o.x = fmaf(p2,    ta.y, ta.x);
    o.y = fmaf(xv2.x, ta.w, ta.z);
    o.z = fmaf(xv2.y, tb.y, tb.x);
    o.w = fmaf(xv2.z, tb.w, tb.z);
    __stcs(reinterpret_cast<float4*>(out + e0 + 2 * CHUNK), o);

    o.x = fmaf(p3,    ta.y, ta.x);
    o.y = fmaf(xv3.x, ta.w, ta.z);
    o.z = fmaf(xv3.y, tb.y, tb.x);
    o.w = fmaf(xv3.z, tb.w, tb.z);
    __stcs(reinterpret_cast<float4*>(out + e0 + 3 * CHUNK), o);
}

// ---------------------------------------------------------------------------
extern "C" void kernel_launch(void* const* d_in, const int* in_sizes, int n_in,
                              void* d_out, int out_size) {
    const float* x = (const float*)d_in[0];
    const float* V = (const float*)d_in[1];
    const float* b = (const float*)d_in[2];
    const float* W = (const float*)d_in[3];
    const float* c = (const float*)d_in[4];
    float* out = (float*)d_out;

    nade_tables<<<D_DIM / 4, 256>>>(V, b, W, c);

    cudaLaunchConfig_t cfg = {};
    cfg.gridDim  = dim3(NQ / 256);        // 3136
    cfg.blockDim = dim3(256);
    cfg.dynamicSmemBytes = 0;
    cfg.stream = 0;
    cudaLaunchAttribute attr[1];
    attr[0].id = cudaLaunchAttributeProgrammaticStreamSerialization;
    attr[0].val.programmaticStreamSerializationAllowed = 1;
    cfg.attrs = attr;
    cfg.numAttrs = 1;
    cudaLaunchKernelEx(&cfg, nade_main, x, out);
}